// round 1
// baseline (speedup 1.0000x reference)
#include <cuda_runtime.h>
#include <cstdint>

#define H 32
#define EPSV 1e-5f
#define N_MAX 10016
#define M_MAX 262144
#define NOUT_MAX 4000000
#define FULLMASK 0xffffffffu

// ---------------- scratch (device globals; no runtime allocation) ----------
__device__ float g_degcnt[N_MAX];
__device__ float g_dinv[N_MAX];
__device__ float g_rdeg[N_MAX];
__device__ float g_h[N_MAX * H];      // x@W (pre-aggregation) for current GCN layer
__device__ float g_agg[N_MAX * H];    // aggregation target, then holds y = agg + h/deg + b
__device__ float g_x[N_MAX * H];      // final node features after layer 2
__device__ float g_xe[M_MAX * H];
__device__ float g_mul[M_MAX * H];
__device__ float g_bmm[(size_t)NOUT_MAX * H];
__device__ float g_colsum[H];
__device__ float g_colsq[H];
__device__ float g_mean[H];
__device__ float g_invstd[H];

// ---------------- zero kernels ----------------------------------------------
__global__ void k_zero_pre(int n_nodes) {
    int i = blockIdx.x * blockDim.x + threadIdx.x;
    int stride = gridDim.x * blockDim.x;
    int tot = n_nodes * H;
    for (int idx = i; idx < tot; idx += stride) g_agg[idx] = 0.f;
    for (int idx = i; idx < n_nodes; idx += stride) g_degcnt[idx] = 0.f;
    if (i < H) { g_colsum[i] = 0.f; g_colsq[i] = 0.f; }
}

__global__ void k_zero_agg(int n_nodes) {
    int i = blockIdx.x * blockDim.x + threadIdx.x;
    int stride = gridDim.x * blockDim.x;
    int tot = n_nodes * H;
    for (int idx = i; idx < tot; idx += stride) g_agg[idx] = 0.f;
}

__global__ void k_zero_bmm(long long tot4) {
    long long i = (long long)blockIdx.x * blockDim.x + threadIdx.x;
    long long stride = (long long)gridDim.x * blockDim.x;
    float4 z = make_float4(0.f, 0.f, 0.f, 0.f);
    float4* p = reinterpret_cast<float4*>(g_bmm);
    for (long long idx = i; idx < tot4; idx += stride) p[idx] = z;
}

// ---------------- degree / normalization ------------------------------------
__global__ void k_deg(const int* __restrict__ dst, int m) {
    int e = blockIdx.x * blockDim.x + threadIdx.x;
    if (e < m) atomicAdd(&g_degcnt[dst[e]], 1.f);
}

__global__ void k_dinv(int n) {
    int i = blockIdx.x * blockDim.x + threadIdx.x;
    if (i < n) {
        float d = g_degcnt[i] + 1.f;
        g_dinv[i] = rsqrtf(d);
        g_rdeg[i] = 1.f / d;
    }
}

// ---------------- node tower -------------------------------------------------
// x0 = emb[x_nodes];  h = x0 @ W1   (warp per node, lane = output channel)
__global__ void k_embed_gemm(const float* __restrict__ emb,
                             const int* __restrict__ x_nodes,
                             const float* __restrict__ w, int n) {
    __shared__ float ws[H * H];
    for (int i = threadIdx.x; i < H * H; i += blockDim.x) ws[i] = w[i];
    __syncthreads();
    int lane = threadIdx.x & 31;
    int row = (blockIdx.x * blockDim.x + threadIdx.x) >> 5;
    if (row >= n) return;
    float v = emb[x_nodes[row] * H + lane];
    float acc = 0.f;
#pragma unroll
    for (int k = 0; k < H; k++)
        acc = fmaf(__shfl_sync(FULLMASK, v, k), ws[k * H + lane], acc);
    g_h[row * H + lane] = acc;
}

// agg[dst] += h[src] * dinv[src]*dinv[dst]   (warp per edge)
__global__ void k_agg(const int* __restrict__ src, const int* __restrict__ dst, int m) {
    int lane = threadIdx.x & 31;
    int e = (blockIdx.x * blockDim.x + threadIdx.x) >> 5;
    if (e >= m) return;
    int s = src[e], d = dst[e];
    float en = g_dinv[s] * g_dinv[d];
    atomicAdd(&g_agg[d * H + lane], g_h[s * H + lane] * en);
}

// y = agg + h/deg + b  (in place into g_agg) + accumulate column sums/sumsq
__global__ void k_post(const float* __restrict__ bias, int n) {
    int lane = threadIdx.x & 31;
    int wid = threadIdx.x >> 5;
    int gw = (blockIdx.x * blockDim.x + threadIdx.x) >> 5;
    int nwarps = (gridDim.x * blockDim.x) >> 5;
    float b = bias[lane];
    float sum = 0.f, sq = 0.f;
    for (int row = gw; row < n; row += nwarps) {
        float y = g_agg[row * H + lane] + g_h[row * H + lane] * g_rdeg[row] + b;
        g_agg[row * H + lane] = y;
        sum += y;
        sq += y * y;
    }
    __shared__ float s_sum[8][32];
    __shared__ float s_sq[8][32];
    s_sum[wid][lane] = sum;
    s_sq[wid][lane] = sq;
    __syncthreads();
    if (threadIdx.x < 32) {
        float ts = 0.f, tq = 0.f;
#pragma unroll
        for (int w = 0; w < 8; w++) { ts += s_sum[w][threadIdx.x]; tq += s_sq[w][threadIdx.x]; }
        atomicAdd(&g_colsum[threadIdx.x], ts);
        atomicAdd(&g_colsq[threadIdx.x], tq);
    }
}

// mean / invstd from accumulated sums; also reset accumulators for next use.
// var = E[h^2] - ms*(2-ms)*mean^2
__global__ void k_statsfin(const float* __restrict__ ms, float inv_n) {
    int c = threadIdx.x;
    if (c < H) {
        float mean = g_colsum[c] * inv_n;
        float m2 = g_colsq[c] * inv_n;
        float msv = ms[c];
        float var = m2 - msv * (2.f - msv) * mean * mean;
        g_mean[c] = mean;
        g_invstd[c] = rsqrtf(var + EPSV);
        g_colsum[c] = 0.f;
        g_colsq[c] = 0.f;
    }
}

// x1 = relu(gnorm(y));  h2 = x1 @ W2  -> g_h (overwrite)
__global__ void k_norm_gemm(const float* __restrict__ gnw, const float* __restrict__ gnb,
                            const float* __restrict__ ms, const float* __restrict__ w2, int n) {
    __shared__ float ws[H * H];
    for (int i = threadIdx.x; i < H * H; i += blockDim.x) ws[i] = w2[i];
    __syncthreads();
    int lane = threadIdx.x & 31;
    int row = (blockIdx.x * blockDim.x + threadIdx.x) >> 5;
    if (row >= n) return;
    float y = g_agg[row * H + lane];
    float xv = gnw[lane] * (y - ms[lane] * g_mean[lane]) * g_invstd[lane] + gnb[lane];
    xv = fmaxf(xv, 0.f);
    float acc = 0.f;
#pragma unroll
    for (int k = 0; k < H; k++)
        acc = fmaf(__shfl_sync(FULLMASK, xv, k), ws[k * H + lane], acc);
    g_h[row * H + lane] = acc;
}

// x = relu(gnorm(y)) -> g_x
__global__ void k_norm_only(const float* __restrict__ gnw, const float* __restrict__ gnb,
                            const float* __restrict__ ms, int n) {
    int lane = threadIdx.x & 31;
    int row = (blockIdx.x * blockDim.x + threadIdx.x) >> 5;
    if (row >= n) return;
    float y = g_agg[row * H + lane];
    float xv = gnw[lane] * (y - ms[lane] * g_mean[lane]) * g_invstd[lane] + gnb[lane];
    g_x[row * H + lane] = fmaxf(xv, 0.f);
}

// ---------------- edge MLPs ---------------------------------------------------
// val = [x[src], x[dst]];  xe = relu(val@W1+b1); mul = relu(val@W2+b2)
__global__ void k_edge_mlp(const int* __restrict__ src, const int* __restrict__ dst,
                           const float* __restrict__ w1, const float* __restrict__ b1,
                           const float* __restrict__ w2, const float* __restrict__ b2, int m) {
    __shared__ float w1s[2 * H * H];
    __shared__ float w2s[2 * H * H];
    for (int i = threadIdx.x; i < 2 * H * H; i += blockDim.x) { w1s[i] = w1[i]; w2s[i] = w2[i]; }
    __syncthreads();
    int lane = threadIdx.x & 31;
    int e = (blockIdx.x * blockDim.x + threadIdx.x) >> 5;
    if (e >= m) return;
    int s = src[e], d = dst[e];
    float xs = g_x[s * H + lane];
    float xd = g_x[d * H + lane];
    float a1 = b1[lane], a2 = b2[lane];
#pragma unroll
    for (int k = 0; k < H; k++) {
        float v = __shfl_sync(FULLMASK, xs, k);
        a1 = fmaf(v, w1s[k * H + lane], a1);
        a2 = fmaf(v, w2s[k * H + lane], a2);
    }
#pragma unroll
    for (int k = 0; k < H; k++) {
        float v = __shfl_sync(FULLMASK, xd, k);
        a1 = fmaf(v, w1s[(H + k) * H + lane], a1);
        a2 = fmaf(v, w2s[(H + k) * H + lane], a2);
    }
    g_xe[e * H + lane] = fmaxf(a1, 0.f);
    g_mul[e * H + lane] = fmaxf(a2, 0.f);
}

// ---------------- sparse-sparse bmm scatter -----------------------------------
__global__ void k_scatter(const int* __restrict__ tri_a, const int* __restrict__ tri_b,
                          const int* __restrict__ tri_seg, int T) {
    int lane = threadIdx.x & 31;
    int t = (blockIdx.x * blockDim.x + threadIdx.x) >> 5;
    if (t >= T) return;
    int a = tri_a[t], b = tri_b[t], sg = tri_seg[t];
    float prod = g_xe[a * H + lane] * g_mul[b * H + lane];
    atomicAdd(&g_bmm[(size_t)sg * H + lane], prod);
}

// ---------------- mlp3 statistics pass (no h materialization) -----------------
__global__ void k_mlp3stats(const float* __restrict__ w3, const float* __restrict__ b3,
                            const float* __restrict__ is_edge, int n) {
    __shared__ float ws[33 * H];
    for (int i = threadIdx.x; i < 33 * H; i += blockDim.x) ws[i] = w3[i];
    __syncthreads();
    int lane = threadIdx.x & 31;
    int wid = threadIdx.x >> 5;
    int gw = (blockIdx.x * blockDim.x + threadIdx.x) >> 5;
    int nwarps = (gridDim.x * blockDim.x) >> 5;
    float bb = b3[lane];
    float w_ie = ws[32 * H + lane];
    float sum = 0.f, sq = 0.f;
    for (int row = gw; row < n; row += nwarps) {
        float v = g_bmm[(size_t)row * H + lane];
        float acc = fmaf(is_edge[row], w_ie, bb);
#pragma unroll
        for (int k = 0; k < H; k++)
            acc = fmaf(__shfl_sync(FULLMASK, v, k), ws[k * H + lane], acc);
        sum += acc;
        sq += acc * acc;
    }
    __shared__ float s_sum[8][32];
    __shared__ float s_sq[8][32];
    s_sum[wid][lane] = sum;
    s_sq[wid][lane] = sq;
    __syncthreads();
    if (threadIdx.x < 32) {
        float ts = 0.f, tq = 0.f;
#pragma unroll
        for (int w = 0; w < 8; w++) { ts += s_sum[w][threadIdx.x]; tq += s_sq[w][threadIdx.x]; }
        atomicAdd(&g_colsum[threadIdx.x], ts);
        atomicAdd(&g_colsq[threadIdx.x], tq);
    }
}

// ---------------- final query kernel ------------------------------------------
__device__ __forceinline__ float compute_xo(int row, int lane, const float* ws,
                                            const float* __restrict__ is_edge,
                                            const float* __restrict__ b3,
                                            const float* __restrict__ gn3w,
                                            const float* __restrict__ gn3b,
                                            const float* __restrict__ gn3ms) {
    float v = g_bmm[(size_t)row * H + lane];
    float acc = fmaf(is_edge[row], ws[32 * H + lane], b3[lane]);
#pragma unroll
    for (int k = 0; k < H; k++)
        acc = fmaf(__shfl_sync(FULLMASK, v, k), ws[k * H + lane], acc);
    float xo = gn3w[lane] * (acc - gn3ms[lane] * g_mean[lane]) * g_invstd[lane] + gn3b[lane];
    return fmaxf(xo, 0.f);
}

__global__ void k_final(const int* __restrict__ pred_idx, const int* __restrict__ trans_perm,
                        const float* __restrict__ pred_mask, const int* __restrict__ pos,
                        const float* __restrict__ is_edge,
                        const float* __restrict__ w3, const float* __restrict__ b3,
                        const float* __restrict__ gn3w, const float* __restrict__ gn3b,
                        const float* __restrict__ gn3ms,
                        const float* __restrict__ lw, const float* __restrict__ lb,
                        float* __restrict__ out, int P) {
    __shared__ float ws[33 * H];
    for (int i = threadIdx.x; i < 33 * H; i += blockDim.x) ws[i] = w3[i];
    __syncthreads();
    int lane = threadIdx.x & 31;
    int p = (blockIdx.x * blockDim.x + threadIdx.x) >> 5;
    if (p >= P) return;
    int r = pred_idx[p];
    int rt = trans_perm[r];
    float mask = pred_mask[p];
    float xo_r = compute_xo(r, lane, ws, is_edge, b3, gn3w, gn3b, gn3ms);
    float xo_t = compute_xo(rt, lane, ws, is_edge, b3, gn3w, gn3b, gn3ms);
    int i0 = pos[2 * p], j0 = pos[2 * p + 1];
    float xx = g_x[i0 * H + lane] * g_x[j0 * H + lane];
    float part = xo_r * xo_t * mask * lw[lane] + xx * lw[H + lane];
#pragma unroll
    for (int off = 16; off; off >>= 1) part += __shfl_down_sync(FULLMASK, part, off);
    if (lane == 0) out[p] = part + lb[0];
}

// ---------------- launch ------------------------------------------------------
extern "C" void kernel_launch(void* const* d_in, const int* in_sizes, int n_in,
                              void* d_out, int out_size) {
    const float* emb     = (const float*)d_in[0];
    const float* gcn1_w  = (const float*)d_in[1];
    const float* gcn1_b  = (const float*)d_in[2];
    const float* gn1_w   = (const float*)d_in[3];
    const float* gn1_b   = (const float*)d_in[4];
    const float* gn1_ms  = (const float*)d_in[5];
    const float* gcn2_w  = (const float*)d_in[6];
    const float* gcn2_b  = (const float*)d_in[7];
    const float* gn2_w   = (const float*)d_in[8];
    const float* gn2_b   = (const float*)d_in[9];
    const float* gn2_ms  = (const float*)d_in[10];
    const float* mlp1_w  = (const float*)d_in[11];
    const float* mlp1_b  = (const float*)d_in[12];
    const float* mlp2_w  = (const float*)d_in[13];
    const float* mlp2_b  = (const float*)d_in[14];
    const float* mlp3_w  = (const float*)d_in[15];
    const float* mlp3_b  = (const float*)d_in[16];
    const float* gn3_w   = (const float*)d_in[17];
    const float* gn3_b   = (const float*)d_in[18];
    const float* gn3_ms  = (const float*)d_in[19];
    const float* lind_w  = (const float*)d_in[20];
    const float* lind_b  = (const float*)d_in[21];
    const float* is_edge = (const float*)d_in[22];
    const float* pred_mask = (const float*)d_in[23];
    const int* x_nodes   = (const int*)d_in[24];
    const int* ei        = (const int*)d_in[25];
    const int* pos       = (const int*)d_in[26];
    const int* tri_a     = (const int*)d_in[27];
    const int* tri_b     = (const int*)d_in[28];
    const int* tri_seg   = (const int*)d_in[29];
    const int* trans_perm= (const int*)d_in[30];
    const int* pred_idx  = (const int*)d_in[31];

    int N     = in_sizes[24];
    int m     = in_sizes[25] / 2;
    int n_out = in_sizes[22];
    int T     = in_sizes[27];
    int P     = in_sizes[23];

    const int* src = ei;
    const int* dst = ei + m;

    int nodeWarpBlocks = (N * H + 255) / 256;
    int edgeWarpBlocks = (int)(((long long)m * H + 255) / 256);
    int triWarpBlocks  = (int)(((long long)T * H + 255) / 256);
    int queryWarpBlocks = (P * H + 255) / 256;

    // zero scratch
    k_zero_pre<<<160, 256>>>(N);
    long long tot4 = ((long long)n_out * H) / 4;
    k_zero_bmm<<<2048, 256>>>(tot4);

    // degrees
    k_deg<<<(m + 255) / 256, 256>>>(dst, m);
    k_dinv<<<(N + 255) / 256, 256>>>(N);

    // GCN layer 1
    k_embed_gemm<<<nodeWarpBlocks, 256>>>(emb, x_nodes, gcn1_w, N);
    k_agg<<<edgeWarpBlocks, 256>>>(src, dst, m);
    k_post<<<120, 256>>>(gcn1_b, N);
    k_statsfin<<<1, 32>>>(gn1_ms, 1.f / (float)N);
    k_norm_gemm<<<nodeWarpBlocks, 256>>>(gn1_w, gn1_b, gn1_ms, gcn2_w, N);

    // GCN layer 2
    k_zero_agg<<<160, 256>>>(N);
    k_agg<<<edgeWarpBlocks, 256>>>(src, dst, m);
    k_post<<<120, 256>>>(gcn2_b, N);
    k_statsfin<<<1, 32>>>(gn2_ms, 1.f / (float)N);
    k_norm_only<<<nodeWarpBlocks, 256>>>(gn2_w, gn2_b, gn2_ms, N);

    // edge MLPs
    k_edge_mlp<<<edgeWarpBlocks, 256>>>(src, dst, mlp1_w, mlp1_b, mlp2_w, mlp2_b, m);

    // sparse-sparse bmm
    k_scatter<<<triWarpBlocks, 256>>>(tri_a, tri_b, tri_seg, T);

    // mlp3 GraphNorm statistics (h recomputed on demand later)
    k_mlp3stats<<<1184, 256>>>(mlp3_w, mlp3_b, is_edge, n_out);
    k_statsfin<<<1, 32>>>(gn3_ms, 1.f / (float)n_out);

    // final query kernel
    k_final<<<queryWarpBlocks, 256>>>(pred_idx, trans_perm, pred_mask, pos, is_edge,
                                      mlp3_w, mlp3_b, gn3_w, gn3_b, gn3_ms,
                                      lind_w, lind_b, (float*)d_out, P);
}